// round 17
// baseline (speedup 1.0000x reference)
#include <cuda_runtime.h>
#include <cuda_bf16.h>
#include <mma.h>

using namespace nvcuda;

#define NB   4
#define HW   4096
#define CH   512
#define QKVN 1536
#define NGRP 32
#define CPG  16
#define GNEPS 1e-5f

#define BM 128
#define BN 128
#define BK 64
#define NSTG 3
#define STG_STRIDE 18432          // bytes per operand tile (128*72*2)
#define SMEMSZ (NSTG * 2 * STG_STRIDE)   // 110592

// ---------------- scratch ----------------
__device__ __nv_bfloat16 g_h[(long)NB * HW * CH];
__device__ __nv_bfloat16 g_qkv[(long)NB * HW * QKVN];
__device__ __nv_bfloat16 g_p[(long)NB * HW * HW];       // bf16 unnormalized probs
__device__ float         g_psum[(long)NB * 128 * HW];   // per-32col-tile row partials
__device__ float         g_rowsum[NB * HW];
__device__ __nv_bfloat16 g_ao[(long)NB * HW * CH];
__device__ __nv_bfloat16 g_wqkv[CH * QKVN];             // [k][n] concat
__device__ __nv_bfloat16 g_wpr[CH * CH];                // [k][n]
__device__ float g_bqkv[QKVN];
__device__ float g_mean[NB * NGRP];
__device__ float g_rstd[NB * NGRP];

__device__ __forceinline__ void cpa16(void* s, const void* g) {
    unsigned sa = (unsigned)__cvta_generic_to_shared(s);
    asm volatile("cp.async.cg.shared.global [%0], [%1], 16;" :: "r"(sa), "l"(g));
}

// ---------------- weight prep ----------------
__global__ __launch_bounds__(256) void prep(const float* __restrict__ wq,
                                            const float* __restrict__ wk,
                                            const float* __restrict__ wv,
                                            const float* __restrict__ wp,
                                            const float* __restrict__ bq,
                                            const float* __restrict__ bk,
                                            const float* __restrict__ bv) {
    int idx = blockIdx.x * 256 + threadIdx.x;
    if (idx < CH * QKVN) {
        int c = idx / QKVN, col = idx - c * QKVN;
        int sel = col >> 9, cc = col & 511;
        const float* w = (sel == 0) ? wq : (sel == 1) ? wk : wv;
        g_wqkv[idx] = __float2bfloat16_rn(w[c * CH + cc]);
        if (idx < QKVN) {
            const float* bb = (idx < 512) ? bq : (idx < 1024) ? bk : bv;
            g_bqkv[idx] = bb[idx & 511];
        }
    } else {
        int j = idx - CH * QKVN;
        if (j < CH * CH) g_wpr[j] = __float2bfloat16_rn(wp[j]);
    }
}

// ---------------- GroupNorm stats ----------------
__global__ __launch_bounds__(256) void gn_stats(const float* __restrict__ x) {
    int bid = blockIdx.x;
    int b = bid >> 5, g = bid & 31;
    const float* base = x + (long)b * HW * CH + g * CPG;
    float s = 0.f, ss = 0.f;
    for (int p = threadIdx.x; p < HW; p += 256) {
        const float4* pp = (const float4*)(base + (long)p * CH);
#pragma unroll
        for (int i = 0; i < 4; i++) {
            float4 v = pp[i];
            s  += v.x + v.y + v.z + v.w;
            ss += v.x * v.x + v.y * v.y + v.z * v.z + v.w * v.w;
        }
    }
    __shared__ float sh[512];
    sh[threadIdx.x] = s; sh[256 + threadIdx.x] = ss;
    __syncthreads();
    for (int o = 128; o > 0; o >>= 1) {
        if (threadIdx.x < o) {
            sh[threadIdx.x] += sh[threadIdx.x + o];
            sh[256 + threadIdx.x] += sh[256 + threadIdx.x + o];
        }
        __syncthreads();
    }
    if (threadIdx.x == 0) {
        const float inv = 1.0f / (HW * CPG);
        float mean = sh[0] * inv;
        float var  = sh[256] * inv - mean * mean;
        g_mean[bid] = mean;
        g_rstd[bid] = rsqrtf(var + GNEPS);
    }
}

// ---------------- GroupNorm apply -> bf16 ----------------
__global__ __launch_bounds__(256) void gn_apply(const float* __restrict__ x,
                                                const float* __restrict__ gamma,
                                                const float* __restrict__ beta) {
    long i = (long)blockIdx.x * 256 + threadIdx.x;
    long i4 = i * 4;
    int b = (int)(i4 >> 21);
    int c = (int)(i4 & (CH - 1));
    int g = c >> 4;
    float mean = g_mean[b * NGRP + g];
    float rstd = g_rstd[b * NGRP + g];
    float4 v  = ((const float4*)x)[i];
    float4 ga = ((const float4*)gamma)[c >> 2];
    float4 be = ((const float4*)beta)[c >> 2];
    __nv_bfloat162 h0 = __floats2bfloat162_rn((v.x - mean) * rstd * ga.x + be.x,
                                              (v.y - mean) * rstd * ga.y + be.y);
    __nv_bfloat162 h1 = __floats2bfloat162_rn((v.z - mean) * rstd * ga.z + be.z,
                                              (v.w - mean) * rstd * ga.w + be.w);
    uint2 u; u.x = *(unsigned*)&h0; u.y = *(unsigned*)&h1;
    ((uint2*)g_h)[i] = u;
}

// ---------------- rowsum reduce: 128 partials per row ----------------
__global__ __launch_bounds__(256) void rowsum_reduce() {
    int gid = blockIdx.x * 256 + threadIdx.x;       // NB*HW threads
    int b = gid >> 12, row = gid & (HW - 1);
    const float* p = g_psum + (long)b * 128 * HW + row;
    float s = 0.f;
#pragma unroll
    for (int t = 0; t < 128; t++) s += p[(long)t * HW];
    g_rowsum[gid] = s;
}

// ---------------- bf16 GEMM: 128x128x64, 3-stage, 8 warps, 64x32 warp tile --
// C = alpha*A@op(B) (+bias)(+res). BCOL: B [N,K] row-major => C = A@B^T.
// EXPP: out = exp(alpha*acc) -> bf16 + row partials.  RSUM: out *= 1/aux[row].
template<bool BCOL, bool BIAS, bool RES, bool OBF, bool EXPP, bool RSUM>
__global__ __launch_bounds__(256, 2)
void gemm_bf16(const __nv_bfloat16* __restrict__ A, const __nv_bfloat16* __restrict__ B,
               const float* __restrict__ bias, const float* __restrict__ res,
               float* __restrict__ aux,
               void* __restrict__ Cv,
               int lda, int ldb, int ldc,
               long sA, long sB, long sC, int K, float alpha) {
    extern __shared__ __align__(16) char smem[];

    const int bz = blockIdx.z;
    A += (long)bz * sA;  B += (long)bz * sB;
    const float* resp = RES ? (res + (long)bz * sC) : nullptr;

    const int bm = blockIdx.y * BM, bn = blockIdx.x * BN;
    const int tid = threadIdx.x, warp = tid >> 5, lane = tid & 31;
    const int wm = warp >> 2, wn = warp & 3;          // 2 x 4 warp grid, 64x32 tile

    wmma::fragment<wmma::accumulator, 16, 16, 16, float> acc[4][2];
#pragma unroll
    for (int i = 0; i < 4; i++)
#pragma unroll
        for (int j = 0; j < 2; j++) wmma::fill_fragment(acc[i][j], 0.0f);

    // staging thread mapping (shared by A and BCOL-B): 128 rows x 64 cols
    const int srow = tid >> 1, sc8 = (tid & 1) * 32;          // 2 cpa16 per row half
    // !BCOL B: 64 rows x 128 cols
    const int brow = tid >> 2, bc8 = (tid & 3) * 32;

    auto stage = [&](int kt, int buf) {
        const int k0 = kt * BK;
        __nv_bfloat16* As = (__nv_bfloat16*)(smem + buf * 2 * STG_STRIDE);
        __nv_bfloat16* Bs = (__nv_bfloat16*)(smem + buf * 2 * STG_STRIDE + STG_STRIDE);
        {
            const __nv_bfloat16* ag = A + (long)(bm + srow) * lda + k0 + sc8;
            cpa16(As + srow * 72 + sc8, ag);
            cpa16(As + srow * 72 + sc8 + 8, ag + 8);
            cpa16(As + srow * 72 + sc8 + 16, ag + 16);
            cpa16(As + srow * 72 + sc8 + 24, ag + 24);
        }
        if (BCOL) {
            const __nv_bfloat16* bg = B + (long)(bn + srow) * ldb + k0 + sc8;
            cpa16(Bs + srow * 72 + sc8, bg);
            cpa16(Bs + srow * 72 + sc8 + 8, bg + 8);
            cpa16(Bs + srow * 72 + sc8 + 16, bg + 16);
            cpa16(Bs + srow * 72 + sc8 + 24, bg + 24);
        } else {
            const __nv_bfloat16* bg = B + (long)(k0 + brow) * ldb + bn + bc8;
            cpa16(Bs + brow * 136 + bc8, bg);
            cpa16(Bs + brow * 136 + bc8 + 8, bg + 8);
            cpa16(Bs + brow * 136 + bc8 + 16, bg + 16);
            cpa16(Bs + brow * 136 + bc8 + 24, bg + 24);
        }
        asm volatile("cp.async.commit_group;" ::: "memory");
    };

    auto compute = [&](int buf) {
        const __nv_bfloat16* As = (const __nv_bfloat16*)(smem + buf * 2 * STG_STRIDE);
        const __nv_bfloat16* Bs = (const __nv_bfloat16*)(smem + buf * 2 * STG_STRIDE + STG_STRIDE);
#pragma unroll
        for (int kk = 0; kk < BK; kk += 16) {
            wmma::fragment<wmma::matrix_a, 16, 16, 16, __nv_bfloat16, wmma::row_major> af[4];
#pragma unroll
            for (int i = 0; i < 4; i++)
                wmma::load_matrix_sync(af[i], As + (wm * 64 + i * 16) * 72 + kk, 72);
            if constexpr (BCOL) {
                wmma::fragment<wmma::matrix_b, 16, 16, 16, __nv_bfloat16, wmma::col_major> bf[2];
#pragma unroll
                for (int j = 0; j < 2; j++)
                    wmma::load_matrix_sync(bf[j], Bs + (wn * 32 + j * 16) * 72 + kk, 72);
#pragma unroll
                for (int i = 0; i < 4; i++)
#pragma unroll
                    for (int j = 0; j < 2; j++)
                        wmma::mma_sync(acc[i][j], af[i], bf[j], acc[i][j]);
            } else {
                wmma::fragment<wmma::matrix_b, 16, 16, 16, __nv_bfloat16, wmma::row_major> bf[2];
#pragma unroll
                for (int j = 0; j < 2; j++)
                    wmma::load_matrix_sync(bf[j], Bs + kk * 136 + wn * 32 + j * 16, 136);
#pragma unroll
                for (int i = 0; i < 4; i++)
#pragma unroll
                    for (int j = 0; j < 2; j++)
                        wmma::mma_sync(acc[i][j], af[i], bf[j], acc[i][j]);
            }
        }
    };

    const int KT = K / BK;
    stage(0, 0);
    stage(1, 1);
    for (int kt = 0; kt < KT; kt++) {
        if (kt + 1 < KT) asm volatile("cp.async.wait_group 1;" ::: "memory");
        else             asm volatile("cp.async.wait_group 0;" ::: "memory");
        __syncthreads();
        if (kt + 2 < KT) {
            int b2 = kt + 2;
            stage(b2, b2 - (b2 / NSTG) * NSTG);
        }
        compute(kt - (kt / NSTG) * NSTG);
    }
    __syncthreads();

    // ---------------- epilogue (staged per-fragment) ----------------
    float* ebuf = (float*)smem + warp * 320;          // 16x20 per warp
    const int r = lane >> 1, cb = (lane & 1) * 8;
#pragma unroll
    for (int i = 0; i < 4; i++) {
        float rs = 0.f;
        const int gm = bm + wm * 64 + i * 16 + r;
#pragma unroll
        for (int j = 0; j < 2; j++) {
            wmma::store_matrix_sync(ebuf, acc[i][j], 20, wmma::mem_row_major);
            __syncwarp();
            float4 v0 = *(const float4*)(ebuf + r * 20 + cb);
            float4 v1 = *(const float4*)(ebuf + r * 20 + cb + 4);
            __syncwarp();
            const int gnc = bn + wn * 32 + j * 16 + cb;
            float o[8] = {v0.x * alpha, v0.y * alpha, v0.z * alpha, v0.w * alpha,
                          v1.x * alpha, v1.y * alpha, v1.z * alpha, v1.w * alpha};
            if (BIAS) {
                float4 b0 = *(const float4*)(bias + gnc);
                float4 b1 = *(const float4*)(bias + gnc + 4);
                o[0] += b0.x; o[1] += b0.y; o[2] += b0.z; o[3] += b0.w;
                o[4] += b1.x; o[5] += b1.y; o[6] += b1.z; o[7] += b1.w;
            }
            if (RES) {
                const float* rp = resp + (long)gm * ldc + gnc;
                float4 r0 = *(const float4*)rp;
                float4 r1 = *(const float4*)(rp + 4);
                o[0] += r0.x; o[1] += r0.y; o[2] += r0.z; o[3] += r0.w;
                o[4] += r1.x; o[5] += r1.y; o[6] += r1.z; o[7] += r1.w;
            }
            if (EXPP) {
#pragma unroll
                for (int e = 0; e < 8; e++) { o[e] = __expf(o[e]); rs += o[e]; }
            }
            if (RSUM) {
                float inv = 1.0f / aux[bz * HW + gm];
#pragma unroll
                for (int e = 0; e < 8; e++) o[e] *= inv;
            }
            if (OBF) {
                __nv_bfloat16* cp = (__nv_bfloat16*)Cv + (long)bz * sC + (long)gm * ldc + gnc;
                __nv_bfloat162 p0 = __floats2bfloat162_rn(o[0], o[1]);
                __nv_bfloat162 p1 = __floats2bfloat162_rn(o[2], o[3]);
                __nv_bfloat162 p2 = __floats2bfloat162_rn(o[4], o[5]);
                __nv_bfloat162 p3 = __floats2bfloat162_rn(o[6], o[7]);
                uint4 u;
                u.x = *(unsigned*)&p0; u.y = *(unsigned*)&p1;
                u.z = *(unsigned*)&p2; u.w = *(unsigned*)&p3;
                *(uint4*)cp = u;
            } else {
                float* cp = (float*)Cv + (long)bz * sC + (long)gm * ldc + gnc;
                *(float4*)cp       = make_float4(o[0], o[1], o[2], o[3]);
                *(float4*)(cp + 4) = make_float4(o[4], o[5], o[6], o[7]);
            }
        }
        if (EXPP) {
            rs += __shfl_xor_sync(0xFFFFFFFFu, rs, 1);
            if (!(lane & 1)) {
                const int tIdx = (bn + wn * 32) >> 5;          // 32-col tile index
                aux[((long)bz * 128 + tIdx) * HW + gm] = rs;
            }
        }
    }
}

// ---------------- launch ----------------
extern "C" void kernel_launch(void* const* d_in, const int* in_sizes, int n_in,
                              void* d_out, int out_size) {
    const float* x     = (const float*)d_in[0];
    const float* gamma = (const float*)d_in[1];
    const float* beta  = (const float*)d_in[2];
    const float* wq = (const float*)d_in[3];
    const float* bq = (const float*)d_in[4];
    const float* wk = (const float*)d_in[5];
    const float* bk = (const float*)d_in[6];
    const float* wv = (const float*)d_in[7];
    const float* bv = (const float*)d_in[8];
    const float* wp = (const float*)d_in[9];
    const float* bp = (const float*)d_in[10];
    float* out = (float*)d_out;

    __nv_bfloat16 *hh, *qkv, *ao, *pr, *wqkvp, *wpr;
    float *bqkvp, *psum, *rowsum;
    cudaGetSymbolAddress((void**)&hh, g_h);
    cudaGetSymbolAddress((void**)&qkv, g_qkv);
    cudaGetSymbolAddress((void**)&ao, g_ao);
    cudaGetSymbolAddress((void**)&pr, g_p);
    cudaGetSymbolAddress((void**)&wqkvp, g_wqkv);
    cudaGetSymbolAddress((void**)&bqkvp, g_bqkv);
    cudaGetSymbolAddress((void**)&wpr, g_wpr);
    cudaGetSymbolAddress((void**)&psum, g_psum);
    cudaGetSymbolAddress((void**)&rowsum, g_rowsum);

    cudaFuncSetAttribute(gemm_bf16<false, true,  false, true,  false, false>, cudaFuncAttributeMaxDynamicSharedMemorySize, SMEMSZ);
    cudaFuncSetAttribute(gemm_bf16<true,  false, false, true,  true,  false>, cudaFuncAttributeMaxDynamicSharedMemorySize, SMEMSZ);
    cudaFuncSetAttribute(gemm_bf16<false, false, false, true,  false, true >, cudaFuncAttributeMaxDynamicSharedMemorySize, SMEMSZ);
    cudaFuncSetAttribute(gemm_bf16<false, true,  true,  false, false, false>, cudaFuncAttributeMaxDynamicSharedMemorySize, SMEMSZ);

    const long sQ = (long)HW * QKVN;
    const long sS = (long)HW * HW;
    const long sO = (long)HW * CH;
    const float scale = 0.044194173824159216f;   // 1/sqrt(512)

    prep<<<(CH * QKVN + CH * CH) / 256, 256>>>(wq, wk, wv, wp, bq, bk, bv);

    gn_stats<<<NB * NGRP, 256>>>(x);
    gn_apply<<<(int)(((long)NB * HW * CH / 4) / 256), 256>>>(x, gamma, beta);

    // fused QKV: [16384,512] @ [512,1536] + bias -> bf16
    gemm_bf16<false, true, false, true, false, false>
        <<<dim3(QKVN / BN, (NB * HW) / BM, 1), 256, SMEMSZ>>>(
        hh, wqkvp, bqkvp, nullptr, nullptr, qkv, CH, QKVN, QKVN, 0, 0, 0, CH, 1.0f);

    // scores+exp: probs = exp(scale * q@k^T) -> bf16 (unnormalized) + row partials
    gemm_bf16<true, false, false, true, true, false>
        <<<dim3(HW / BN, HW / BM, NB), 256, SMEMSZ>>>(
        qkv, qkv + 512, nullptr, nullptr, psum, pr, QKVN, QKVN, HW, sQ, sQ, sS, CH, scale);

    // rowsum
    rowsum_reduce<<<(NB * HW) / 256, 256>>>();

    // attn @ v with rowsum normalization -> bf16
    gemm_bf16<false, false, false, true, false, true>
        <<<dim3(CH / BN, HW / BM, NB), 256, SMEMSZ>>>(
        pr, qkv + 1024, nullptr, nullptr, rowsum, ao, HW, QKVN, CH, sS, sQ, sO, HW, 1.0f);

    // proj + residual -> fp32 out
    gemm_bf16<false, true, true, false, false, false>
        <<<dim3(CH / BN, (NB * HW) / BM, 1), 256, SMEMSZ>>>(
        ao, wpr, bp, x, nullptr, out, CH, CH, CH, 0, 0, 0, CH, 1.0f);
}